// round 2
// baseline (speedup 1.0000x reference)
#include <cuda_runtime.h>
#include <cuda_bf16.h>
#include <math.h>

// Problem constants (fixed for this problem instance)
#define BSZ   8
#define TMAX  256
#define UMAX  64
#define EDIM  512
#define PDIM  512
#define JDIM  512
#define VDIM  1024
#define MAX_STU (BSZ * TMAX * UMAX)   // 131072

// -------- scratch (device globals; no allocation allowed) --------
__device__ float g_emb_proj[VDIM * JDIM];            // 2 MB : emb @ W_pred^T
__device__ float g_enc_proj[BSZ * TMAX * JDIM];      // 4 MB : enc_out @ W_enc^T + b_enc
__device__ float g_h[(size_t)MAX_STU * JDIM];        // 256 MB : tanh joint rows

// ----------------------------------------------------------------
// Generic tiled SGEMM:  C[M,N] = A[M,K] @ B[N,K]^T (+ bias[N])
// A row-major [M,K], B row-major [N,K]  (both K-contiguous: "NT" gemm)
// BM=64, BN=64, BK=16, 256 threads, 4x4 register microtile.
// N and K must be multiples of 64/16; M may be ragged (guarded).
// ----------------------------------------------------------------
#define BM 64
#define BN 64
#define BK 16

__global__ __launch_bounds__(256) void gemm_nt_kernel(
    const float* __restrict__ A, const float* __restrict__ B,
    const float* __restrict__ bias, float* __restrict__ C,
    int M, int N, int K)
{
    __shared__ float As[BM][BK];       // [m][k]
    __shared__ float Bs[BK][BN];       // [k][n] (transposed on load)

    const int tid = threadIdx.x;
    const int tx = tid & 15;           // n direction (16)
    const int ty = tid >> 4;           // m direction (16)
    const int bm = blockIdx.x * BM;
    const int bn = blockIdx.y * BN;

    // load mapping: each thread loads one float4 of A and one of B per tile
    const int lr = tid >> 2;           // row within tile 0..63
    const int lc = (tid & 3) * 4;      // k offset 0,4,8,12

    float acc[4][4];
#pragma unroll
    for (int i = 0; i < 4; i++)
#pragma unroll
        for (int j = 0; j < 4; j++) acc[i][j] = 0.0f;

    for (int k0 = 0; k0 < K; k0 += BK) {
        // ---- load A tile (guarded on M) ----
        float4 av = make_float4(0.f, 0.f, 0.f, 0.f);
        if (bm + lr < M)
            av = *(const float4*)(A + (size_t)(bm + lr) * K + k0 + lc);
        *(float4*)(&As[lr][lc]) = av;

        // ---- load B tile, store transposed ----
        float4 bv = *(const float4*)(B + (size_t)(bn + lr) * K + k0 + lc);
        Bs[lc + 0][lr] = bv.x;
        Bs[lc + 1][lr] = bv.y;
        Bs[lc + 2][lr] = bv.z;
        Bs[lc + 3][lr] = bv.w;

        __syncthreads();

        // ---- compute ----
#pragma unroll
        for (int kk = 0; kk < BK; kk += 4) {
            float a_[4][4];   // [m][k]
#pragma unroll
            for (int i = 0; i < 4; i++) {
                float4 t = *(const float4*)(&As[ty * 4 + i][kk]);
                a_[i][0] = t.x; a_[i][1] = t.y; a_[i][2] = t.z; a_[i][3] = t.w;
            }
#pragma unroll
            for (int s = 0; s < 4; s++) {
                float4 b4 = *(const float4*)(&Bs[kk + s][tx * 4]);
#pragma unroll
                for (int i = 0; i < 4; i++) {
                    acc[i][0] = fmaf(a_[i][s], b4.x, acc[i][0]);
                    acc[i][1] = fmaf(a_[i][s], b4.y, acc[i][1]);
                    acc[i][2] = fmaf(a_[i][s], b4.z, acc[i][2]);
                    acc[i][3] = fmaf(a_[i][s], b4.w, acc[i][3]);
                }
            }
        }
        __syncthreads();
    }

    // ---- epilogue ----
    const int n0 = bn + tx * 4;
    float4 bj = make_float4(0.f, 0.f, 0.f, 0.f);
    if (bias) bj = *(const float4*)(bias + n0);
#pragma unroll
    for (int i = 0; i < 4; i++) {
        int m = bm + ty * 4 + i;
        if (m < M) {
            float4 v;
            v.x = acc[i][0] + bj.x;
            v.y = acc[i][1] + bj.y;
            v.z = acc[i][2] + bj.z;
            v.w = acc[i][3] + bj.w;
            *(float4*)(C + (size_t)m * N + n0) = v;
        }
    }
}

// ----------------------------------------------------------------
// Build h[STU, 512] = tanh(enc_proj[b,t,:] + emb_proj[prefix[b,u],:] + b_pred)
// One block per gathered row, 128 threads, float4 per thread.
// ----------------------------------------------------------------
__global__ __launch_bounds__(128) void build_h_kernel(
    const int* __restrict__ gidx, const int* __restrict__ prefix,
    const float* __restrict__ enc_proj, const float* __restrict__ emb_proj,
    const float* __restrict__ b_pred, float* __restrict__ h, int STU)
{
    int row = blockIdx.x;
    if (row >= STU) return;
    int idx = gidx[row];
    int b = idx / (TMAX * UMAX);
    int rem = idx - b * (TMAX * UMAX);
    int t = rem / UMAX;
    int u = rem - t * UMAX;
    int tok = prefix[b * UMAX + u];

    const float4* er = (const float4*)(enc_proj + ((size_t)b * TMAX + t) * JDIM);
    const float4* pr = (const float4*)(emb_proj + (size_t)tok * JDIM);
    const float4* bp = (const float4*)b_pred;
    float4* hr = (float4*)(h + (size_t)row * JDIM);

    int j = threadIdx.x;   // 128 threads * 4 floats = 512
    float4 e = er[j], p = pr[j], bb = bp[j];
    float4 o;
    o.x = tanhf(e.x + p.x + bb.x);
    o.y = tanhf(e.y + p.y + bb.y);
    o.z = tanhf(e.z + p.z + bb.z);
    o.w = tanhf(e.w + p.w + bb.w);
    hr[j] = o;
}

// ----------------------------------------------------------------
extern "C" void kernel_launch(void* const* d_in, const int* in_sizes, int n_in,
                              void* d_out, int out_size)
{
    const float* enc_out = (const float*)d_in[0];   // [B, TMAX, E]
    const int*   prefix  = (const int*)  d_in[1];   // [B, UMAX]
    // d_in[2]=in_lens, d_in[3]=tgt_lens : not needed (gather_idx encodes validity)
    const int*   gidx    = (const int*)  d_in[4];   // [STU]
    const float* emb     = (const float*)d_in[5];   // [V, P]
    const float* W_enc   = (const float*)d_in[6];   // [J, E]
    const float* b_enc   = (const float*)d_in[7];   // [J]
    const float* W_pred  = (const float*)d_in[8];   // [J, P]
    const float* b_pred  = (const float*)d_in[9];   // [J]
    const float* W_join  = (const float*)d_in[10];  // [V, J]
    const float* b_join  = (const float*)d_in[11];  // [V]
    float* out = (float*)d_out;                     // [STU, V]

    const int STU = in_sizes[4];

    float *p_emb_proj, *p_enc_proj, *p_h;
    cudaGetSymbolAddress((void**)&p_emb_proj, g_emb_proj);
    cudaGetSymbolAddress((void**)&p_enc_proj, g_enc_proj);
    cudaGetSymbolAddress((void**)&p_h,        g_h);

    // K1: emb_proj[V,J] = emb @ W_pred^T  (bias added later in build_h)
    gemm_nt_kernel<<<dim3(VDIM / BM, JDIM / BN), 256>>>(
        emb, W_pred, nullptr, p_emb_proj, VDIM, JDIM, PDIM);

    // K2: enc_proj[B*TMAX, J] = enc_out @ W_enc^T + b_enc
    gemm_nt_kernel<<<dim3((BSZ * TMAX) / BM, JDIM / BN), 256>>>(
        enc_out, W_enc, b_enc, p_enc_proj, BSZ * TMAX, JDIM, EDIM);

    // K3: gather + broadcast-add + tanh -> h[STU, J]
    build_h_kernel<<<STU, 128>>>(gidx, prefix, p_enc_proj, p_emb_proj,
                                 b_pred, p_h, STU);

    // K4: logits[STU, V] = h @ W_join^T + b_join   (the 78-GFLOP GEMM)
    gemm_nt_kernel<<<dim3((STU + BM - 1) / BM, VDIM / BN), 256>>>(
        p_h, W_join, b_join, out, STU, VDIM, JDIM);
}

// round 4
// speedup vs baseline: 2.7660x; 2.7660x over previous
#include <cuda_runtime.h>
#include <cuda_bf16.h>
#include <cstdint>
#include <math.h>

// Problem constants
#define BSZ   8
#define TMAX  256
#define UMAX  64
#define EDIM  512
#define PDIM  512
#define JDIM  512
#define VDIM  1024
#define MAX_STU (BSZ * TMAX * UMAX)   // 131072

// -------- scratch (device globals; no allocation allowed) --------
__device__ float g_emb_proj[VDIM * JDIM];            // 2 MB
__device__ float g_enc_proj[BSZ * TMAX * JDIM];      // 4 MB
__device__ float g_wj[VDIM * JDIM];                  // 2 MB : W_join pre-rounded to tf32
__device__ float g_h[(size_t)MAX_STU * JDIM];        // 256 MB : tanh rows (tf32-rounded)

__device__ __forceinline__ uint32_t smem_u32(const void* p) {
    uint32_t a;
    asm("{ .reg .u64 t; cvta.to.shared.u64 t, %1; cvt.u32.u64 %0, t; }" : "=r"(a) : "l"(p));
    return a;
}
__device__ __forceinline__ float to_tf32(float x) {
    float r; asm("cvt.rna.tf32.f32 %0, %1;" : "=f"(r) : "f"(x)); return r;
}

#define MMA_TF32(d, a, b) \
    asm volatile("mma.sync.aligned.m16n8k8.row.col.f32.tf32.tf32.f32 " \
        "{%0,%1,%2,%3}, {%4,%5,%6,%7}, {%8,%9}, {%0,%1,%2,%3};" \
        : "+f"((d)[0]), "+f"((d)[1]), "+f"((d)[2]), "+f"((d)[3]) \
        : "r"((a)[0]), "r"((a)[1]), "r"((a)[2]), "r"((a)[3]), \
          "r"((b)[0]), "r"((b)[1]))

// ====================================================================
// K4: C[M, ldc] = A[M,512] @ B[ldc,512]^T + bias  via tf32 mma.sync
// BM=128, BN=128, BK=32; 256 threads; 8 warps (2 m x 4 n), warp tile 64x32.
// A and B must already be tf32-rounded fp32.
// ====================================================================
#define SMP 36                       // smem row pitch in floats (32 + 4 pad)
#define SM_TILE (128 * SMP)          // floats per tile buffer
#define SM_GEMM_BYTES (4 * SM_TILE * 4)   // A0,A1,B0,B1

__global__ __launch_bounds__(256, 1) void join_gemm_mma(
    const float* __restrict__ A, const float* __restrict__ B,
    const float* __restrict__ bias, float* __restrict__ C,
    int M, int ldc)
{
    extern __shared__ float sm[];
    float* Abuf[2] = { sm,               sm + SM_TILE };
    float* Bbuf[2] = { sm + 2 * SM_TILE, sm + 3 * SM_TILE };

    const int tid  = threadIdx.x;
    const int wid  = tid >> 5, lane = tid & 31;
    const int g    = lane >> 2, tg = lane & 3;
    const int wm   = (wid & 1) * 64;       // warp row offset in tile
    const int wn   = (wid >> 1) * 32;      // warp col offset in tile
    const int bm   = blockIdx.x * 128;
    const int bn   = blockIdx.y * 128;

    float acc[4][4][4];
#pragma unroll
    for (int i = 0; i < 4; i++)
#pragma unroll
        for (int j = 0; j < 4; j++)
#pragma unroll
            for (int q = 0; q < 4; q++) acc[i][j][q] = 0.0f;

    // load-mapping constants: 1024 16B-chunks per tile, 4 per thread
    const int lrow = tid >> 3;             // 0..31 row group base (x4)
    const int lkc  = (tid & 7) * 4;        // k offset 0..28

    // ---- tile loader ----
    auto load_tile = [&](int kt, int buf) {
        const int k0 = kt * 32;
#pragma unroll
        for (int i = 0; i < 4; i++) {
            int row = lrow + i * 32;
            const float* src = A + (size_t)(bm + row) * JDIM + k0 + lkc;
            uint32_t dst = smem_u32(&Abuf[buf][row * SMP + lkc]);
            int sz = (bm + row < M) ? 16 : 0;
            asm volatile("cp.async.ca.shared.global [%0], [%1], 16, %2;\n"
                         :: "r"(dst), "l"(src), "r"(sz));
        }
#pragma unroll
        for (int i = 0; i < 4; i++) {
            int row = lrow + i * 32;
            const float* src = B + (size_t)(bn + row) * JDIM + k0 + lkc;
            uint32_t dst = smem_u32(&Bbuf[buf][row * SMP + lkc]);
            asm volatile("cp.async.ca.shared.global [%0], [%1], 16;\n"
                         :: "r"(dst), "l"(src));
        }
        asm volatile("cp.async.commit_group;\n" ::: "memory");
    };

    load_tile(0, 0);
    load_tile(1, 1);

    for (int kt = 0; kt < 16; kt++) {
        if (kt < 15) asm volatile("cp.async.wait_group 1;\n" ::: "memory");
        else         asm volatile("cp.async.wait_group 0;\n" ::: "memory");
        __syncthreads();

        const float* As = Abuf[kt & 1];
        const float* Bs = Bbuf[kt & 1];
#pragma unroll
        for (int ks = 0; ks < 4; ks++) {
            const int k = ks * 8;
            uint32_t a[4][4], b[4][2];
#pragma unroll
            for (int ma = 0; ma < 4; ma++) {
                const float* ap = &As[(wm + ma * 16 + g) * SMP + k + tg];
                a[ma][0] = __float_as_uint(ap[0]);
                a[ma][1] = __float_as_uint(ap[8 * SMP]);
                a[ma][2] = __float_as_uint(ap[4]);
                a[ma][3] = __float_as_uint(ap[8 * SMP + 4]);
            }
#pragma unroll
            for (int na = 0; na < 4; na++) {
                const float* bp = &Bs[(wn + na * 8 + g) * SMP + k + tg];
                b[na][0] = __float_as_uint(bp[0]);
                b[na][1] = __float_as_uint(bp[4]);
            }
#pragma unroll
            for (int ma = 0; ma < 4; ma++)
#pragma unroll
                for (int na = 0; na < 4; na++)
                    MMA_TF32(acc[ma][na], a[ma], b[na]);
        }
        __syncthreads();
        if (kt + 2 < 16) load_tile(kt + 2, kt & 1);
    }

    // ---- epilogue: bias add + store ----
#pragma unroll
    for (int ma = 0; ma < 4; ma++) {
        const int r0 = bm + wm + ma * 16 + g;
#pragma unroll
        for (int na = 0; na < 4; na++) {
            const int col = bn + wn + na * 8 + 2 * tg;
            float2 bv = *(const float2*)(bias + col);
            if (r0 < M) {
                float2 o = make_float2(acc[ma][na][0] + bv.x, acc[ma][na][1] + bv.y);
                *(float2*)(C + (size_t)r0 * ldc + col) = o;
            }
            if (r0 + 8 < M) {
                float2 o = make_float2(acc[ma][na][2] + bv.x, acc[ma][na][3] + bv.y);
                *(float2*)(C + (size_t)(r0 + 8) * ldc + col) = o;
            }
        }
    }
}

// ================ fp32 SGEMM (small projections K1/K2) ================
#define BM 64
#define BN 64
#define BK 16

__global__ __launch_bounds__(256) void gemm_nt_kernel(
    const float* __restrict__ A, const float* __restrict__ B,
    const float* __restrict__ bias, float* __restrict__ C,
    int M, int N, int K)
{
    __shared__ float As[BM][BK];
    __shared__ float Bs[BK][BN];

    const int tid = threadIdx.x;
    const int tx = tid & 15;
    const int ty = tid >> 4;
    const int bm = blockIdx.x * BM;
    const int bn = blockIdx.y * BN;
    const int lr = tid >> 2;
    const int lc = (tid & 3) * 4;

    float acc[4][4];
#pragma unroll
    for (int i = 0; i < 4; i++)
#pragma unroll
        for (int j = 0; j < 4; j++) acc[i][j] = 0.0f;

    for (int k0 = 0; k0 < K; k0 += BK) {
        float4 av = make_float4(0.f, 0.f, 0.f, 0.f);
        if (bm + lr < M)
            av = *(const float4*)(A + (size_t)(bm + lr) * K + k0 + lc);
        *(float4*)(&As[lr][lc]) = av;

        float4 bv = *(const float4*)(B + (size_t)(bn + lr) * K + k0 + lc);
        Bs[lc + 0][lr] = bv.x;
        Bs[lc + 1][lr] = bv.y;
        Bs[lc + 2][lr] = bv.z;
        Bs[lc + 3][lr] = bv.w;

        __syncthreads();
#pragma unroll
        for (int kk = 0; kk < BK; kk += 4) {
            float a_[4][4];
#pragma unroll
            for (int i = 0; i < 4; i++) {
                float4 t = *(const float4*)(&As[ty * 4 + i][kk]);
                a_[i][0] = t.x; a_[i][1] = t.y; a_[i][2] = t.z; a_[i][3] = t.w;
            }
#pragma unroll
            for (int s = 0; s < 4; s++) {
                float4 b4 = *(const float4*)(&Bs[kk + s][tx * 4]);
#pragma unroll
                for (int i = 0; i < 4; i++) {
                    acc[i][0] = fmaf(a_[i][s], b4.x, acc[i][0]);
                    acc[i][1] = fmaf(a_[i][s], b4.y, acc[i][1]);
                    acc[i][2] = fmaf(a_[i][s], b4.z, acc[i][2]);
                    acc[i][3] = fmaf(a_[i][s], b4.w, acc[i][3]);
                }
            }
        }
        __syncthreads();
    }

    const int n0 = bn + tx * 4;
    float4 bj = make_float4(0.f, 0.f, 0.f, 0.f);
    if (bias) bj = *(const float4*)(bias + n0);
#pragma unroll
    for (int i = 0; i < 4; i++) {
        int m = bm + ty * 4 + i;
        if (m < M) {
            float4 v;
            v.x = acc[i][0] + bj.x;
            v.y = acc[i][1] + bj.y;
            v.z = acc[i][2] + bj.z;
            v.w = acc[i][3] + bj.w;
            *(float4*)(C + (size_t)m * N + n0) = v;
        }
    }
}

// ---------------- gather + broadcast-add + tanh (tf32-rounded output) ----------------
__global__ __launch_bounds__(128) void build_h_kernel(
    const int* __restrict__ gidx, const int* __restrict__ prefix,
    const float* __restrict__ enc_proj, const float* __restrict__ emb_proj,
    const float* __restrict__ b_pred, float* __restrict__ h, int STU)
{
    int row = blockIdx.x;
    if (row >= STU) return;
    int idx = gidx[row];
    int b = idx / (TMAX * UMAX);
    int rem = idx - b * (TMAX * UMAX);
    int t = rem / UMAX;
    int u = rem - t * UMAX;
    int tok = prefix[b * UMAX + u];

    const float4* er = (const float4*)(enc_proj + ((size_t)b * TMAX + t) * JDIM);
    const float4* pr = (const float4*)(emb_proj + (size_t)tok * JDIM);
    const float4* bp = (const float4*)b_pred;
    float4* hr = (float4*)(h + (size_t)row * JDIM);

    int j = threadIdx.x;
    float4 e = er[j], p = pr[j], bb = bp[j];
    float4 o;
    o.x = to_tf32(tanhf(e.x + p.x + bb.x));
    o.y = to_tf32(tanhf(e.y + p.y + bb.y));
    o.z = to_tf32(tanhf(e.z + p.z + bb.z));
    o.w = to_tf32(tanhf(e.w + p.w + bb.w));
    hr[j] = o;
}

// ---------------- pre-round W_join to tf32 ----------------
__global__ __launch_bounds__(256) void cvt_tf32_kernel(
    const float* __restrict__ in, float* __restrict__ out, int n4)
{
    int i = blockIdx.x * blockDim.x + threadIdx.x;
    if (i < n4) {
        float4 v = ((const float4*)in)[i];
        v.x = to_tf32(v.x); v.y = to_tf32(v.y);
        v.z = to_tf32(v.z); v.w = to_tf32(v.w);
        ((float4*)out)[i] = v;
    }
}

// ----------------------------------------------------------------
extern "C" void kernel_launch(void* const* d_in, const int* in_sizes, int n_in,
                              void* d_out, int out_size)
{
    const float* enc_out = (const float*)d_in[0];
    const int*   prefix  = (const int*)  d_in[1];
    const int*   gidx    = (const int*)  d_in[4];
    const float* emb     = (const float*)d_in[5];
    const float* W_enc   = (const float*)d_in[6];
    const float* b_enc   = (const float*)d_in[7];
    const float* W_pred  = (const float*)d_in[8];
    const float* b_pred  = (const float*)d_in[9];
    const float* W_join  = (const float*)d_in[10];
    const float* b_join  = (const float*)d_in[11];
    float* out = (float*)d_out;

    const int STU = in_sizes[4];

    float *p_emb_proj, *p_enc_proj, *p_h, *p_wj;
    cudaGetSymbolAddress((void**)&p_emb_proj, g_emb_proj);
    cudaGetSymbolAddress((void**)&p_enc_proj, g_enc_proj);
    cudaGetSymbolAddress((void**)&p_h,        g_h);
    cudaGetSymbolAddress((void**)&p_wj,       g_wj);

    static int attr_set = 0;
    if (!attr_set) {
        cudaFuncSetAttribute(join_gemm_mma,
                             cudaFuncAttributeMaxDynamicSharedMemorySize, SM_GEMM_BYTES);
        attr_set = 1;
    }

    // K0: pre-round W_join to tf32
    cvt_tf32_kernel<<<(VDIM * JDIM / 4 + 255) / 256, 256>>>(W_join, p_wj, VDIM * JDIM / 4);

    // K1: emb_proj[V,J] = emb @ W_pred^T   (fp32)
    gemm_nt_kernel<<<dim3(VDIM / BM, JDIM / BN), 256>>>(
        emb, W_pred, nullptr, p_emb_proj, VDIM, JDIM, PDIM);

    // K2: enc_proj[B*TMAX, J] = enc_out @ W_enc^T + b_enc   (fp32)
    gemm_nt_kernel<<<dim3((BSZ * TMAX) / BM, JDIM / BN), 256>>>(
        enc_out, W_enc, b_enc, p_enc_proj, BSZ * TMAX, JDIM, EDIM);

    // K3: gather + tanh -> h[STU, J]  (tf32-rounded)
    build_h_kernel<<<STU, 128>>>(gidx, prefix, p_enc_proj, p_emb_proj,
                                 b_pred, p_h, STU);

    // K4: logits[STU, V] = h @ W_join^T + b_join  — tf32 mma.sync
    dim3 grid((STU + 127) / 128, VDIM / 128);
    join_gemm_mma<<<grid, 256, SM_GEMM_BYTES>>>(p_h, p_wj, b_join, out, STU, VDIM);
}

// round 5
// speedup vs baseline: 5.4674x; 1.9767x over previous
#include <cuda_runtime.h>
#include <cuda_fp16.h>
#include <cstdint>
#include <math.h>

// Problem constants
#define BSZ   8
#define TMAX  256
#define UMAX  64
#define EDIM  512
#define PDIM  512
#define JDIM  512
#define VDIM  1024
#define MAX_STU (BSZ * TMAX * UMAX)   // 131072

// -------- scratch (device globals) --------
__device__ float  g_emb_proj[VDIM * JDIM];            // 2 MB
__device__ float  g_enc_proj[BSZ * TMAX * JDIM];      // 4 MB
__device__ __half g_wjh[VDIM * JDIM];                 // 1 MB : W_join fp16
__device__ __half g_h[(size_t)MAX_STU * JDIM];        // 128 MB : tanh rows fp16

__device__ __forceinline__ uint32_t smem_u32(const void* p) {
    uint32_t a;
    asm("{ .reg .u64 t; cvta.to.shared.u64 t, %1; cvt.u32.u64 %0, t; }" : "=r"(a) : "l"(p));
    return a;
}

#define LDSM_X4(r0, r1, r2, r3, addr) \
    asm volatile("ldmatrix.sync.aligned.m8n8.x4.shared.b16 {%0,%1,%2,%3}, [%4];" \
        : "=r"(r0), "=r"(r1), "=r"(r2), "=r"(r3) : "r"(addr))

#define MMA_F16(d, a, b0, b1) \
    asm volatile("mma.sync.aligned.m16n8k16.row.col.f32.f16.f16.f32 " \
        "{%0,%1,%2,%3}, {%4,%5,%6,%7}, {%8,%9}, {%0,%1,%2,%3};" \
        : "+f"((d)[0]), "+f"((d)[1]), "+f"((d)[2]), "+f"((d)[3]) \
        : "r"((a)[0]), "r"((a)[1]), "r"((a)[2]), "r"((a)[3]), \
          "r"(b0), "r"(b1))

// ====================================================================
// K4: C[M,1024] = A[M,512]fp16 @ B[1024,512]fp16^T + bias (fp32 out)
// BM=128, BN=256, BK=64; 256 threads; 8 warps 2(m)x4(n), warp tile 64x64.
// Smem: rows of 64 halves (128B), XOR swizzle on 16B chunks.
// ====================================================================
#define AT_HALVES (128 * 64)          // 8192 halves per A buffer
#define BT_HALVES (256 * 64)          // 16384 halves per B buffer
#define SM_K4_BYTES ((2 * AT_HALVES + 2 * BT_HALVES) * 2)   // 98304 B

__global__ __launch_bounds__(256, 1) void join_gemm_f16(
    const __half* __restrict__ A, const __half* __restrict__ B,
    const float* __restrict__ bias, float* __restrict__ C, int M)
{
    extern __shared__ __half smh[];
    __half* Abuf[2] = { smh,                 smh + AT_HALVES };
    __half* Bbuf[2] = { smh + 2 * AT_HALVES, smh + 2 * AT_HALVES + BT_HALVES };

    const int tid  = threadIdx.x;
    const int wid  = tid >> 5, lane = tid & 31;
    const int g    = lane >> 2, tg = lane & 3;
    const int wm   = (wid & 1) * 64;      // warp m offset
    const int wn   = (wid >> 1) * 64;     // warp n offset
    const int bm   = blockIdx.x * 128;
    const int bn   = blockIdx.y * 256;

    float acc[4][8][4];
#pragma unroll
    for (int i = 0; i < 4; i++)
#pragma unroll
        for (int j = 0; j < 8; j++)
#pragma unroll
            for (int q = 0; q < 4; q++) acc[i][j][q] = 0.0f;

    // ---- tile loader: 16B chunks, XOR swizzle: dst = row*64 + (chunk^ (row&7))*8
    auto load_tile = [&](int kt, int buf) {
        const int k0 = kt * 64;
        // A: 128 rows x 8 chunks = 1024, 4 per thread
#pragma unroll
        for (int t = 0; t < 4; t++) {
            int i = tid + t * 256;
            int row = i >> 3, ch = i & 7;
            const __half* src = A + (size_t)(bm + row) * JDIM + k0 + ch * 8;
            uint32_t dst = smem_u32(&Abuf[buf][row * 64 + ((ch ^ (row & 7)) * 8)]);
            int sz = (bm + row < M) ? 16 : 0;
            asm volatile("cp.async.ca.shared.global [%0], [%1], 16, %2;\n"
                         :: "r"(dst), "l"(src), "r"(sz));
        }
        // B: 256 rows x 8 chunks = 2048, 8 per thread
#pragma unroll
        for (int t = 0; t < 8; t++) {
            int i = tid + t * 256;
            int row = i >> 3, ch = i & 7;
            const __half* src = B + (size_t)(bn + row) * JDIM + k0 + ch * 8;
            uint32_t dst = smem_u32(&Bbuf[buf][row * 64 + ((ch ^ (row & 7)) * 8)]);
            asm volatile("cp.async.ca.shared.global [%0], [%1], 16;\n"
                         :: "r"(dst), "l"(src));
        }
        asm volatile("cp.async.commit_group;\n" ::: "memory");
    };

    load_tile(0, 0);
    load_tile(1, 1);

    for (int kt = 0; kt < 8; kt++) {
        if (kt < 7) asm volatile("cp.async.wait_group 1;\n" ::: "memory");
        else        asm volatile("cp.async.wait_group 0;\n" ::: "memory");
        __syncthreads();

        const __half* As = Abuf[kt & 1];
        const __half* Bs = Bbuf[kt & 1];
#pragma unroll
        for (int ks = 0; ks < 4; ks++) {            // k16 steps within BK=64
            uint32_t a[4][4], b[4][4];
            // A frags: 4 x ldmatrix.x4 (16x16 tiles)
#pragma unroll
            for (int ma = 0; ma < 4; ma++) {
                int row = wm + ma * 16 + (lane & 15);
                int ch  = ks * 2 + (lane >> 4);
                uint32_t ad = smem_u32(&As[row * 64 + ((ch ^ (row & 7)) * 8)]);
                LDSM_X4(a[ma][0], a[ma][1], a[ma][2], a[ma][3], ad);
            }
            // B frags: 4 x ldmatrix.x4, each covers two n8 tiles
#pragma unroll
            for (int p = 0; p < 4; p++) {
                int row = wn + p * 16 + ((lane >> 4) << 3) + (lane & 7);
                int ch  = ks * 2 + ((lane >> 3) & 1);
                uint32_t bd = smem_u32(&Bs[row * 64 + ((ch ^ (row & 7)) * 8)]);
                LDSM_X4(b[p][0], b[p][1], b[p][2], b[p][3], bd);
            }
#pragma unroll
            for (int ma = 0; ma < 4; ma++)
#pragma unroll
                for (int p = 0; p < 4; p++) {
                    MMA_F16(acc[ma][2 * p + 0], a[ma], b[p][0], b[p][1]);
                    MMA_F16(acc[ma][2 * p + 1], a[ma], b[p][2], b[p][3]);
                }
        }
        __syncthreads();
        if (kt + 2 < 8) load_tile(kt + 2, kt & 1);
    }

    // ---- epilogue: bias add + fp32 store ----
#pragma unroll
    for (int ma = 0; ma < 4; ma++) {
        const int r0 = bm + wm + ma * 16 + g;
#pragma unroll
        for (int nb = 0; nb < 8; nb++) {
            const int col = bn + wn + nb * 8 + 2 * tg;
            float2 bv = *(const float2*)(bias + col);
            if (r0 < M) {
                float2 o = make_float2(acc[ma][nb][0] + bv.x, acc[ma][nb][1] + bv.y);
                *(float2*)(C + (size_t)r0 * VDIM + col) = o;
            }
            if (r0 + 8 < M) {
                float2 o = make_float2(acc[ma][nb][2] + bv.x, acc[ma][nb][3] + bv.y);
                *(float2*)(C + (size_t)(r0 + 8) * VDIM + col) = o;
            }
        }
    }
}

// ================ fp32 SGEMM (small projections K1/K2) ================
#define BM 64
#define BN 64
#define BK 16

__global__ __launch_bounds__(256) void gemm_nt_kernel(
    const float* __restrict__ A, const float* __restrict__ B,
    const float* __restrict__ bias, float* __restrict__ C,
    int M, int N, int K)
{
    __shared__ float As[BM][BK];
    __shared__ float Bs[BK][BN];

    const int tid = threadIdx.x;
    const int tx = tid & 15;
    const int ty = tid >> 4;
    const int bm = blockIdx.x * BM;
    const int bn = blockIdx.y * BN;
    const int lr = tid >> 2;
    const int lc = (tid & 3) * 4;

    float acc[4][4];
#pragma unroll
    for (int i = 0; i < 4; i++)
#pragma unroll
        for (int j = 0; j < 4; j++) acc[i][j] = 0.0f;

    for (int k0 = 0; k0 < K; k0 += BK) {
        float4 av = make_float4(0.f, 0.f, 0.f, 0.f);
        if (bm + lr < M)
            av = *(const float4*)(A + (size_t)(bm + lr) * K + k0 + lc);
        *(float4*)(&As[lr][lc]) = av;

        float4 bv = *(const float4*)(B + (size_t)(bn + lr) * K + k0 + lc);
        Bs[lc + 0][lr] = bv.x;
        Bs[lc + 1][lr] = bv.y;
        Bs[lc + 2][lr] = bv.z;
        Bs[lc + 3][lr] = bv.w;

        __syncthreads();
#pragma unroll
        for (int kk = 0; kk < BK; kk += 4) {
            float a_[4][4];
#pragma unroll
            for (int i = 0; i < 4; i++) {
                float4 t = *(const float4*)(&As[ty * 4 + i][kk]);
                a_[i][0] = t.x; a_[i][1] = t.y; a_[i][2] = t.z; a_[i][3] = t.w;
            }
#pragma unroll
            for (int s = 0; s < 4; s++) {
                float4 b4 = *(const float4*)(&Bs[kk + s][tx * 4]);
#pragma unroll
                for (int i = 0; i < 4; i++) {
                    acc[i][0] = fmaf(a_[i][s], b4.x, acc[i][0]);
                    acc[i][1] = fmaf(a_[i][s], b4.y, acc[i][1]);
                    acc[i][2] = fmaf(a_[i][s], b4.z, acc[i][2]);
                    acc[i][3] = fmaf(a_[i][s], b4.w, acc[i][3]);
                }
            }
        }
        __syncthreads();
    }

    const int n0 = bn + tx * 4;
    float4 bj = make_float4(0.f, 0.f, 0.f, 0.f);
    if (bias) bj = *(const float4*)(bias + n0);
#pragma unroll
    for (int i = 0; i < 4; i++) {
        int m = bm + ty * 4 + i;
        if (m < M) {
            float4 v;
            v.x = acc[i][0] + bj.x;
            v.y = acc[i][1] + bj.y;
            v.z = acc[i][2] + bj.z;
            v.w = acc[i][3] + bj.w;
            *(float4*)(C + (size_t)m * N + n0) = v;
        }
    }
}

// ---------------- gather + broadcast-add + tanh -> fp16 h ----------------
__global__ __launch_bounds__(128) void build_h_kernel(
    const int* __restrict__ gidx, const int* __restrict__ prefix,
    const float* __restrict__ enc_proj, const float* __restrict__ emb_proj,
    const float* __restrict__ b_pred, __half* __restrict__ h, int STU)
{
    int row = blockIdx.x;
    if (row >= STU) return;
    int idx = gidx[row];
    int b = idx / (TMAX * UMAX);
    int rem = idx - b * (TMAX * UMAX);
    int t = rem / UMAX;
    int u = rem - t * UMAX;
    int tok = prefix[b * UMAX + u];

    const float4* er = (const float4*)(enc_proj + ((size_t)b * TMAX + t) * JDIM);
    const float4* pr = (const float4*)(emb_proj + (size_t)tok * JDIM);
    const float4* bp = (const float4*)b_pred;
    __half2* hr = (__half2*)(h + (size_t)row * JDIM);

    int j = threadIdx.x;
    float4 e = er[j], p = pr[j], bb = bp[j];
    float2 lo = make_float2(tanhf(e.x + p.x + bb.x), tanhf(e.y + p.y + bb.y));
    float2 hi = make_float2(tanhf(e.z + p.z + bb.z), tanhf(e.w + p.w + bb.w));
    hr[2 * j + 0] = __float22half2_rn(lo);
    hr[2 * j + 1] = __float22half2_rn(hi);
}

// ---------------- convert W_join fp32 -> fp16 ----------------
__global__ __launch_bounds__(256) void cvt_f16_kernel(
    const float* __restrict__ in, __half* __restrict__ out, int n4)
{
    int i = blockIdx.x * blockDim.x + threadIdx.x;
    if (i < n4) {
        float4 v = ((const float4*)in)[i];
        __half2* o = (__half2*)(out + 4 * (size_t)i);
        o[0] = __float22half2_rn(make_float2(v.x, v.y));
        o[1] = __float22half2_rn(make_float2(v.z, v.w));
    }
}

// ----------------------------------------------------------------
extern "C" void kernel_launch(void* const* d_in, const int* in_sizes, int n_in,
                              void* d_out, int out_size)
{
    const float* enc_out = (const float*)d_in[0];
    const int*   prefix  = (const int*)  d_in[1];
    const int*   gidx    = (const int*)  d_in[4];
    const float* emb     = (const float*)d_in[5];
    const float* W_enc   = (const float*)d_in[6];
    const float* b_enc   = (const float*)d_in[7];
    const float* W_pred  = (const float*)d_in[8];
    const float* b_pred  = (const float*)d_in[9];
    const float* W_join  = (const float*)d_in[10];
    const float* b_join  = (const float*)d_in[11];
    float* out = (float*)d_out;

    const int STU = in_sizes[4];

    float  *p_emb_proj, *p_enc_proj;
    __half *p_h, *p_wjh;
    cudaGetSymbolAddress((void**)&p_emb_proj, g_emb_proj);
    cudaGetSymbolAddress((void**)&p_enc_proj, g_enc_proj);
    cudaGetSymbolAddress((void**)&p_h,        g_h);
    cudaGetSymbolAddress((void**)&p_wjh,      g_wjh);

    cudaFuncSetAttribute(join_gemm_f16,
                         cudaFuncAttributeMaxDynamicSharedMemorySize, SM_K4_BYTES);

    // K0: W_join -> fp16
    cvt_f16_kernel<<<(VDIM * JDIM / 4 + 255) / 256, 256>>>(W_join, p_wjh, VDIM * JDIM / 4);

    // K1: emb_proj[V,J] = emb @ W_pred^T   (fp32)
    gemm_nt_kernel<<<dim3(VDIM / BM, JDIM / BN), 256>>>(
        emb, W_pred, nullptr, p_emb_proj, VDIM, JDIM, PDIM);

    // K2: enc_proj[B*TMAX, J] = enc_out @ W_enc^T + b_enc   (fp32)
    gemm_nt_kernel<<<dim3((BSZ * TMAX) / BM, JDIM / BN), 256>>>(
        enc_out, W_enc, b_enc, p_enc_proj, BSZ * TMAX, JDIM, EDIM);

    // K3: gather + tanh -> h[STU, J] fp16
    build_h_kernel<<<STU, 128>>>(gidx, prefix, p_enc_proj, p_emb_proj,
                                 b_pred, p_h, STU);

    // K4: logits[STU, V] = h @ W_join^T + b_join  — fp16 mma.sync
    dim3 grid((STU + 127) / 128, VDIM / 256);
    join_gemm_f16<<<grid, 256, SM_K4_BYTES>>>(p_h, p_wjh, b_join, out, STU);
}